// round 7
// baseline (speedup 1.0000x reference)
#include <cuda_runtime.h>

#define CCH 128
#define OCH 128
#define HH  56
#define WW  56
#define BB  32

// scratch: intermediate activations + quantized (transposed) weights
__device__ float g_t[(size_t)BB * CCH * HH * WW];     // ~51.4 MB
__device__ float g_w1[9 * CCH * OCH];                  // [i][c][o]
__device__ float g_w2[9 * CCH * OCH];

// Effective LSQ alpha, matching jax grad_scale forward rounding exactly:
//   g computed in double (numpy), cast to f32 per use;
//   a_eff = fl(a*g32) + fl(a*fl32(1-g))
__device__ __forceinline__ float lsq_alpha_eff(float a, double g) {
    float s32 = (float)g;
    float om  = (float)(1.0 - g);
    return __fadd_rn(__fmul_rn(a, s32), __fmul_rn(a, om));
}

// wq_t[i][c][o] = round(clip(W[i][o][c]/a_eff, -4, 3)) * a_eff
__global__ void quant_w_kernel(const float* __restrict__ W,
                               const float* __restrict__ a_w,
                               float* __restrict__ wt) {
    int idx = blockIdx.x * blockDim.x + threadIdx.x;
    if (idx >= 9 * CCH * OCH) return;
    int o = idx % OCH;
    int c = (idx / OCH) % CCH;
    int i = idx / (OCH * CCH);
    const double gw = 1.0 / sqrt((double)(OCH * CCH * 3));   // 1/sqrt(49152)
    float a = lsq_alpha_eff(a_w[i], gw);
    float v = __fdiv_rn(W[((size_t)i * OCH + o) * CCH + c], a);
    v = fminf(fmaxf(v, -4.f), 3.f);
    wt[idx] = __fmul_rn(rintf(v), a);
}

// One block = one (b, h) output row: out[b][0..127][h][0..55]
// 224 threads: og = tid&31 (4 o each), wg = tid>>5 (8 w each)
__global__ __launch_bounds__(224, 1)
void conv_kernel(const float* __restrict__ xin,       // [B][C][H][W]
                 const float* __restrict__ wqt,       // [9][C][O], i = dw*3+dh
                 const float* __restrict__ ap_ptr,    // scalar alpha_p
                 const float* __restrict__ gamma, const float* __restrict__ beta,
                 const float* __restrict__ mean,  const float* __restrict__ var,
                 const float* __restrict__ resid,
                 float* __restrict__ out,
                 int add_res) {
    extern __shared__ float smem[];
    float* xs = smem;                    // [3][128][58], col offset +1 (pad)
    float* ws = smem + 3 * CCH * 58;     // [3 dw][32 cc][128 o]

    const int h   = blockIdx.x;
    const int b   = blockIdx.y;
    const int tid = threadIdx.x;
    const int og  = tid & 31;
    const int wg  = tid >> 5;
    const int o0  = og * 4;
    const int wb  = wg * 8;

    // stage 3 padded input rows
    for (int idx = tid; idx < 3 * CCH * 58; idx += 224) {
        int wi = idx % 58;
        int rc = idx / 58;
        int c  = rc % CCH;
        int r  = rc / CCH;
        int hs = h + r - 1;
        int w  = wi - 1;
        float v = 0.f;
        if ((unsigned)hs < HH && (unsigned)w < WW)
            v = xin[(((size_t)b * CCH + c) * HH + hs) * WW + w];
        xs[idx] = v;
    }

    // effective psum alpha (jax grad_scale forward) — provably == ap for
    // power-of-2 ap, but compute it the reference's way regardless.
    const double gp = 1.0 / sqrt((double)BB * OCH * HH * WW * 3.0); // 1/sqrt(38535168)
    const float ap = lsq_alpha_eff(ap_ptr[0], gp);

    float out_acc[4][8];
    #pragma unroll
    for (int oi = 0; oi < 4; ++oi)
        #pragma unroll
        for (int wi = 0; wi < 8; ++wi) out_acc[oi][wi] = 0.f;

    for (int r = 0; r < 3; ++r) {           // r = dh (input row h+r-1)
        float facc[3][4][8];
        #pragma unroll
        for (int dw = 0; dw < 3; ++dw)
            #pragma unroll
            for (int oi = 0; oi < 4; ++oi)
                #pragma unroll
                for (int wi = 0; wi < 8; ++wi) facc[dw][oi][wi] = 0.f;

        for (int ch = 0; ch < 4; ++ch) {    // 32-channel chunks
            __syncthreads();                // xs ready / prev ws consumed
            for (int idx = tid; idx < 3 * 32 * OCH; idx += 224) {
                int o  = idx & (OCH - 1);
                int t2 = idx >> 7;          // dw*32 + cc
                int cc = t2 & 31;
                int dw = t2 >> 5;
                ws[idx] = wqt[((size_t)(dw * 3 + r) * CCH + (ch * 32 + cc)) * OCH + o];
            }
            __syncthreads();

            const float* xbase = xs + (r * CCH + ch * 32) * 58 + wb;
            #pragma unroll 2
            for (int cc = 0; cc < 32; ++cc) {
                float xv[10];
                #pragma unroll
                for (int j = 0; j < 10; ++j) xv[j] = xbase[cc * 58 + j];
                #pragma unroll
                for (int dw = 0; dw < 3; ++dw) {
                    float4 w4 = *(const float4*)(ws + (dw * 32 + cc) * OCH + o0);
                    float wa0 = w4.x, wa1 = w4.y, wa2 = w4.z, wa3 = w4.w;
                    #pragma unroll
                    for (int wi = 0; wi < 8; ++wi) {
                        float xvv = xv[wi + dw];
                        facc[dw][0][wi] = __fmaf_rn(wa0, xvv, facc[dw][0][wi]);
                        facc[dw][1][wi] = __fmaf_rn(wa1, xvv, facc[dw][1][wi]);
                        facc[dw][2][wi] = __fmaf_rn(wa2, xvv, facc[dw][2][wi]);
                        facc[dw][3][wi] = __fmaf_rn(wa3, xvv, facc[dw][3][wi]);
                    }
                }
            }
        }

        // per-shift LSQ psum quantization, then accumulate (exact multiples of ap)
        #pragma unroll
        for (int dw = 0; dw < 3; ++dw)
            #pragma unroll
            for (int oi = 0; oi < 4; ++oi)
                #pragma unroll
                for (int wi = 0; wi < 8; ++wi) {
                    float q = fminf(fmaxf(__fdiv_rn(facc[dw][oi][wi], ap), -4.f), 3.f);
                    out_acc[oi][wi] = __fadd_rn(out_acc[oi][wi], __fmul_rn(rintf(q), ap));
                }
    }

    // epilogue: BN (+residual) + ReLU with jax-matching rounding (NO fma contraction)
    const size_t obase0 = ((size_t)b * OCH) * (HH * WW) + (size_t)h * WW + wb;
    #pragma unroll
    for (int oi = 0; oi < 4; ++oi) {
        int o = o0 + oi;
        float invs = __fdiv_rn(gamma[o], sqrtf(__fadd_rn(var[o], 1e-5f)));
        float sh   = __fadd_rn(beta[o], -__fmul_rn(mean[o], invs));
        size_t base = obase0 + (size_t)o * (HH * WW);
        float vals[8];
        #pragma unroll
        for (int wi = 0; wi < 8; ++wi)
            vals[wi] = __fadd_rn(__fmul_rn(out_acc[oi][wi], invs), sh);
        if (add_res) {
            float4 r0 = *(const float4*)(resid + base);
            float4 r1 = *(const float4*)(resid + base + 4);
            vals[0] = __fadd_rn(vals[0], r0.x); vals[1] = __fadd_rn(vals[1], r0.y);
            vals[2] = __fadd_rn(vals[2], r0.z); vals[3] = __fadd_rn(vals[3], r0.w);
            vals[4] = __fadd_rn(vals[4], r1.x); vals[5] = __fadd_rn(vals[5], r1.y);
            vals[6] = __fadd_rn(vals[6], r1.z); vals[7] = __fadd_rn(vals[7], r1.w);
        }
        float4 s0 = make_float4(fmaxf(vals[0], 0.f), fmaxf(vals[1], 0.f),
                                fmaxf(vals[2], 0.f), fmaxf(vals[3], 0.f));
        float4 s1 = make_float4(fmaxf(vals[4], 0.f), fmaxf(vals[5], 0.f),
                                fmaxf(vals[6], 0.f), fmaxf(vals[7], 0.f));
        *(float4*)(out + base)     = s0;
        *(float4*)(out + base + 4) = s1;
    }
}

extern "C" void kernel_launch(void* const* d_in, const int* in_sizes, int n_in,
                              void* d_out, int out_size) {
    const float* x    = (const float*)d_in[0];
    const float* W1   = (const float*)d_in[1];
    const float* a_w1 = (const float*)d_in[2];
    const float* W2   = (const float*)d_in[3];
    const float* a_w2 = (const float*)d_in[4];
    const float* a_p1 = (const float*)d_in[5];
    const float* a_p2 = (const float*)d_in[6];
    const float* g1   = (const float*)d_in[7];
    const float* b1   = (const float*)d_in[8];
    const float* m1   = (const float*)d_in[9];
    const float* v1   = (const float*)d_in[10];
    const float* g2   = (const float*)d_in[11];
    const float* b2   = (const float*)d_in[12];
    const float* m2   = (const float*)d_in[13];
    const float* v2   = (const float*)d_in[14];
    float* out = (float*)d_out;

    float *t, *w1q, *w2q;
    cudaGetSymbolAddress((void**)&t,   g_t);
    cudaGetSymbolAddress((void**)&w1q, g_w1);
    cudaGetSymbolAddress((void**)&w2q, g_w2);

    const int smem_bytes = (3 * CCH * 58 + 3 * 32 * OCH) * (int)sizeof(float); // 138240
    cudaFuncSetAttribute(conv_kernel, cudaFuncAttributeMaxDynamicSharedMemorySize, smem_bytes);

    const int nw = 9 * CCH * OCH;
    quant_w_kernel<<<(nw + 255) / 256, 256>>>(W1, a_w1, w1q);
    quant_w_kernel<<<(nw + 255) / 256, 256>>>(W2, a_w2, w2q);

    dim3 grid(HH, BB);
    conv_kernel<<<grid, 224, smem_bytes>>>(x, w1q, a_p1, g1, b1, m1, v1, nullptr, t, 0);
    conv_kernel<<<grid, 224, smem_bytes>>>(t, w2q, a_p2, g2, b2, m2, v2, x, out, 1);
}